// round 3
// baseline (speedup 1.0000x reference)
#include <cuda_runtime.h>
#include <cuda_fp16.h>
#include <cuda_fp8.h>
#include <cstdint>

// ---------------------------------------------------------------------------
// out[M,N] = (fp8(x*xs) @ fp8(w^T*ws)^T) * (1/xs)*(1/ws), fp32 out
// M=16384, N=4096, K=4096
// R3: operands stored as e4m3 BYTES; GEMM uses family-portable
// mma.sync.m16n8k32.f32.e4m3.e4m3.f32. Byte-level fragment layout is identical
// to the f16 m16n8k16 path, so smem layout / ldmatrix addressing is unchanged
// (128-byte rows), but each k-chunk now covers K=128 elements.
// ---------------------------------------------------------------------------
#define MDIM 16384
#define NDIM 4096
#define KDIM 4096

#define BM 128
#define BN 128
#define BKB 128              // K-bytes per stage row (=128 fp8 elements)
#define STAGES 4
#define KITERS (KDIM / BKB)  // 32

// SW128-style swizzle: XOR 16B-chunk index (bits[6:4]) with row%8 (bits[9:7])
#define SWZ(o) ((o) ^ (((o) >> 3) & 0x70))

// ---------------------------------------------------------------------------
// Device scratch (allocation-free)
// ---------------------------------------------------------------------------
__device__ __align__(1024) unsigned char g_x8[(size_t)MDIM * KDIM]; // 64 MB fp8 x [M,K]
__device__ __align__(1024) unsigned char g_w8[(size_t)NDIM * KDIM]; // 16 MB fp8 w^T [N,K]
__device__ unsigned int g_amax_bits[2];
__device__ float g_scales[3]; // xs, ws, (1/xs)*(1/ws)

// ---------------------------------------------------------------------------
// PTX helpers (family-portable: cp.async, ldmatrix, mma.sync)
// ---------------------------------------------------------------------------
__device__ __forceinline__ uint32_t smem_u32(const void* p) {
    uint32_t a;
    asm("{ .reg .u64 t; cvta.to.shared.u64 t, %1; cvt.u32.u64 %0, t; }" : "=r"(a) : "l"(p));
    return a;
}

#define CP_ASYNC16(dst, gsrc) \
    asm volatile("cp.async.cg.shared.global [%0], [%1], 16;" :: "r"(dst), "l"(gsrc) : "memory")
#define CP_COMMIT() asm volatile("cp.async.commit_group;" ::: "memory")
#define CP_WAIT(n)  asm volatile("cp.async.wait_group %0;" :: "n"(n) : "memory")

#define LDSM_X4(r0, r1, r2, r3, addr) \
    asm volatile("ldmatrix.sync.aligned.m8n8.x4.shared.b16 {%0,%1,%2,%3}, [%4];" \
        : "=r"(r0), "=r"(r1), "=r"(r2), "=r"(r3) : "r"(addr))

// fp8 e4m3 MMA, K=32, fp32 accumulate (PTX ISA: sm_89+, family-portable)
#define MMA16832(c, a, b) \
    asm volatile("mma.sync.aligned.m16n8k32.row.col.f32.e4m3.e4m3.f32 " \
        "{%0,%1,%2,%3}, {%4,%5,%6,%7}, {%8,%9}, {%0,%1,%2,%3};" \
        : "+f"((c)[0]), "+f"((c)[1]), "+f"((c)[2]), "+f"((c)[3]) \
        : "r"((a)[0]), "r"((a)[1]), "r"((a)[2]), "r"((a)[3]), "r"((b)[0]), "r"((b)[1]))

// ---------------------------------------------------------------------------
// Phase 1: amax reductions + scales
// ---------------------------------------------------------------------------
__global__ void reset_kernel() {
    g_amax_bits[0] = 0u;
    g_amax_bits[1] = 0u;
}

__global__ void amax_kernel(const float* __restrict__ p, long long n4, int slot) {
    float m = 0.0f;
    const float4* v = (const float4*)p;
    long long stride = (long long)gridDim.x * blockDim.x;
    for (long long i = (long long)blockIdx.x * blockDim.x + threadIdx.x; i < n4; i += stride) {
        float4 a = v[i];
        m = fmaxf(m, fmaxf(fmaxf(fabsf(a.x), fabsf(a.y)), fmaxf(fabsf(a.z), fabsf(a.w))));
    }
    #pragma unroll
    for (int o = 16; o; o >>= 1) m = fmaxf(m, __shfl_xor_sync(0xFFFFFFFFu, m, o));
    __shared__ float sm[32];
    if ((threadIdx.x & 31) == 0) sm[threadIdx.x >> 5] = m;
    __syncthreads();
    if (threadIdx.x < 32) {
        m = (threadIdx.x < (blockDim.x >> 5)) ? sm[threadIdx.x] : 0.0f;
        #pragma unroll
        for (int o = 16; o; o >>= 1) m = fmaxf(m, __shfl_xor_sync(0xFFFFFFFFu, m, o));
        if (threadIdx.x == 0) atomicMax(&g_amax_bits[slot], __float_as_uint(m));
    }
}

__global__ void scale_kernel() {
    float ax = __uint_as_float(g_amax_bits[0]);
    float aw = __uint_as_float(g_amax_bits[1]);
    float xs = 448.0f / fmaxf(ax, 1e-12f);
    float ws = 448.0f / fmaxf(aw, 1e-12f);
    g_scales[0] = xs;
    g_scales[1] = ws;
    g_scales[2] = (1.0f / xs) * (1.0f / ws);
}

__device__ __forceinline__ unsigned char q8(float v, float s) {
    return (unsigned char)__nv_cvt_float_to_fp8(v * s, __NV_SATFINITE, __NV_E4M3);
}

// ---------------------------------------------------------------------------
// Phase 2: quantize x [M,K] fp32 -> g_x8 [M,K] e4m3 bytes
// one thread = 16 elements (64B in, 16B out)
// ---------------------------------------------------------------------------
__global__ void quant_x_kernel(const float* __restrict__ x) {
    size_t i = ((size_t)blockIdx.x * blockDim.x + threadIdx.x) * 16;
    float s = g_scales[0];
    uint32_t o[4];
    #pragma unroll
    for (int j = 0; j < 4; ++j) {
        float4 v = *(const float4*)(x + i + j * 4);
        o[j] = (uint32_t)q8(v.x, s)
             | ((uint32_t)q8(v.y, s) << 8)
             | ((uint32_t)q8(v.z, s) << 16)
             | ((uint32_t)q8(v.w, s) << 24);
    }
    *(uint4*)(g_x8 + i) = make_uint4(o[0], o[1], o[2], o[3]);
}

// ---------------------------------------------------------------------------
// Phase 3: weight [K,N] fp32 -> g_w8 [N,K] e4m3 bytes (transpose + quantize)
// 128x128 tile per block, 256 threads
// ---------------------------------------------------------------------------
__global__ void quant_w_kernel(const float* __restrict__ w) {
    __shared__ unsigned char s[128 * 129];
    int k0 = blockIdx.x * 128;
    int n0 = blockIdx.y * 128;
    float ws = g_scales[1];
    #pragma unroll 4
    for (int it = 0; it < 16; ++it) {
        int p = it * 1024 + threadIdx.x * 4;   // element index within 128x128 tile
        int kl = p >> 7, nl = p & 127;
        float4 v = *(const float4*)&w[(size_t)(k0 + kl) * NDIM + n0 + nl];
        s[kl * 129 + nl + 0] = q8(v.x, ws);
        s[kl * 129 + nl + 1] = q8(v.y, ws);
        s[kl * 129 + nl + 2] = q8(v.z, ws);
        s[kl * 129 + nl + 3] = q8(v.w, ws);
    }
    __syncthreads();
    // 128 n-rows x 8 groups of 16 k-bytes = 1024 tasks, 4 per thread
    #pragma unroll
    for (int it = 0; it < 4; ++it) {
        int t = it * 256 + threadIdx.x;
        int nl = t >> 3, kg = t & 7;
        uint32_t o[4];
        #pragma unroll
        for (int j = 0; j < 4; ++j) {
            int kb = kg * 16 + j * 4;
            o[j] = (uint32_t)s[(kb + 0) * 129 + nl]
                 | ((uint32_t)s[(kb + 1) * 129 + nl] << 8)
                 | ((uint32_t)s[(kb + 2) * 129 + nl] << 16)
                 | ((uint32_t)s[(kb + 3) * 129 + nl] << 24);
        }
        *(uint4*)(g_w8 + (size_t)(n0 + nl) * KDIM + k0 + kg * 16) = make_uint4(o[0], o[1], o[2], o[3]);
    }
}

// ---------------------------------------------------------------------------
// Phase 4: GEMM. A = g_x8 [M,K] row-major, B = g_w8 [N,K] (TN).
// CTA 128x128, 128 K-bytes/stage, 4-stage cp.async pipeline,
// 8 warps of 64x32, fp8 m16n8k32 MMA.
// ---------------------------------------------------------------------------
#define A_STAGE_BYTES (BM * BKB)             // 16384
#define B_STAGE_BYTES (BN * BKB)             // 16384
#define SMEM_TOTAL (STAGES * (A_STAGE_BYTES + B_STAGE_BYTES))  // 131072

__global__ void __launch_bounds__(256, 1) gemm_kernel(float* __restrict__ out) {
    extern __shared__ char smem[];
    const uint32_t sb = smem_u32(smem);
    const int tid = threadIdx.x;
    const int lane = tid & 31;
    const int wid = tid >> 5;
    const int warp_m = wid & 1;   // 2 warps along M (64 rows each)
    const int warp_n = wid >> 1;  // 4 warps along N (32 cols each)
    const int m0 = blockIdx.y * BM;
    const int n0 = blockIdx.x * BN;

    const uint64_t Ag = __cvta_generic_to_global(g_x8 + (size_t)m0 * KDIM);
    const uint64_t Bg = __cvta_generic_to_global(g_w8 + (size_t)n0 * KDIM);

    // copy one (stage, kblk): A/B tiles are 128 rows x 8 chunks of 16B
    auto load_stage = [&](int stage, int kblk) {
        uint32_t abase = sb + stage * A_STAGE_BYTES;
        uint32_t bbase = sb + STAGES * A_STAGE_BYTES + stage * B_STAGE_BYTES;
        uint64_t koff = (uint64_t)kblk * BKB;   // bytes into a K row
        #pragma unroll
        for (int i = 0; i < 4; ++i) {
            int c = tid + i * 256;
            int row = c >> 3, col = c & 7;
            CP_ASYNC16(abase + SWZ(row * 128 + col * 16),
                       Ag + (uint64_t)row * KDIM + koff + col * 16);
        }
        #pragma unroll
        for (int i = 0; i < 4; ++i) {
            int c = tid + i * 256;
            int row = c >> 3, col = c & 7;
            CP_ASYNC16(bbase + SWZ(row * 128 + col * 16),
                       Bg + (uint64_t)row * KDIM + koff + col * 16);
        }
        CP_COMMIT();
    };

    // prologue: fill 3 stages
    load_stage(0, 0);
    load_stage(1, 1);
    load_stage(2, 2);

    float acc[4][4][4];
    #pragma unroll
    for (int mi = 0; mi < 4; ++mi)
        #pragma unroll
        for (int nj = 0; nj < 4; ++nj)
            #pragma unroll
            for (int r = 0; r < 4; ++r) acc[mi][nj][r] = 0.0f;

    // per-lane ldmatrix address components (byte offsets within 128B rows)
    const uint32_t a_row = warp_m * 64 + (lane & 15);
    const uint32_t a_kb  = (uint32_t)((lane >> 4) << 4);
    const uint32_t b_n   = warp_n * 32 + (lane & 7) + ((lane >> 4) << 3);
    const uint32_t b_kb  = (uint32_t)(((lane >> 3) & 1) << 4);

    #pragma unroll 1
    for (int it = 0; it < KITERS; ++it) {
        CP_WAIT(2);
        __syncthreads();
        if (it + 3 < KITERS) load_stage((it + 3) & 3, it + 3);

        uint32_t abase = sb + (it & 3) * A_STAGE_BYTES;
        uint32_t bbase = sb + STAGES * A_STAGE_BYTES + (it & 3) * B_STAGE_BYTES;

        // 4 k-steps of 32 fp8 (32 bytes) each
        #pragma unroll
        for (int ks = 0; ks < 4; ++ks) {
            uint32_t a[4][4], b[4][2];
            #pragma unroll
            for (int mi = 0; mi < 4; ++mi) {
                uint32_t off = (a_row + mi * 16) * 128 + ks * 32 + a_kb;
                LDSM_X4(a[mi][0], a[mi][1], a[mi][2], a[mi][3], abase + SWZ(off));
            }
            #pragma unroll
            for (int bh = 0; bh < 2; ++bh) {
                uint32_t off = (b_n + bh * 16) * 128 + ks * 32 + b_kb;
                LDSM_X4(b[2 * bh][0], b[2 * bh][1], b[2 * bh + 1][0], b[2 * bh + 1][1],
                        bbase + SWZ(off));
            }
            #pragma unroll
            for (int mi = 0; mi < 4; ++mi)
                #pragma unroll
                for (int nj = 0; nj < 4; ++nj)
                    MMA16832(acc[mi][nj], a[mi], b[nj]);
        }
    }

    // epilogue: scale + store fp32
    const float cs = g_scales[2];
    const int row_base = m0 + warp_m * 64 + (lane >> 2);
    const int col_base = n0 + warp_n * 32 + (lane & 3) * 2;
    #pragma unroll
    for (int mi = 0; mi < 4; ++mi) {
        #pragma unroll
        for (int nj = 0; nj < 4; ++nj) {
            int r = row_base + mi * 16;
            int c = col_base + nj * 8;
            float2 v0 = make_float2(acc[mi][nj][0] * cs, acc[mi][nj][1] * cs);
            float2 v1 = make_float2(acc[mi][nj][2] * cs, acc[mi][nj][3] * cs);
            *(float2*)(out + (size_t)r * NDIM + c) = v0;
            *(float2*)(out + (size_t)(r + 8) * NDIM + c) = v1;
        }
    }
}

// ---------------------------------------------------------------------------
// Launch
// ---------------------------------------------------------------------------
extern "C" void kernel_launch(void* const* d_in, const int* in_sizes, int n_in,
                              void* d_out, int out_size) {
    const float* x = (const float*)d_in[0];
    const float* w = (const float*)d_in[1];
    float* out = (float*)d_out;

    cudaFuncSetAttribute(gemm_kernel, cudaFuncAttributeMaxDynamicSharedMemorySize, SMEM_TOTAL);

    reset_kernel<<<1, 1>>>();
    amax_kernel<<<2048, 256>>>(x, (long long)MDIM * KDIM / 4, 0);
    amax_kernel<<<512, 256>>>(w, (long long)KDIM * NDIM / 4, 1);
    scale_kernel<<<1, 1>>>();
    quant_x_kernel<<<(int)(((size_t)MDIM * KDIM / 16) / 256), 256>>>(x);
    quant_w_kernel<<<dim3(KDIM / 128, NDIM / 128), 256>>>(w);
    gemm_kernel<<<dim3(NDIM / BN, MDIM / BM), 256, SMEM_TOTAL>>>(out);
}

// round 4
// speedup vs baseline: 1.0115x; 1.0115x over previous
#include <cuda_runtime.h>
#include <cuda_fp16.h>
#include <cuda_fp8.h>
#include <cstdint>

// ---------------------------------------------------------------------------
// out[M,N] = (fp8(x*xs) @ fp8(w^T*ws)^T) * (1/xs)*(1/ws), fp32 out
// M=16384, N=4096, K=4096
// R4: fp8 m16n8k32 path with CTA 128x256, warp tile 64x64 (8 warps),
// 4-stage cp.async pipeline (192 KB smem). Goal: amortize sync/LDSM overhead
// over 2x more MMA work per iteration (measured mma.sync MAC-rate floor).
// ---------------------------------------------------------------------------
#define MDIM 16384
#define NDIM 4096
#define KDIM 4096

#define BM 128
#define BN 256
#define BKB 128              // K-bytes per stage row (=128 fp8 elements)
#define STAGES 4
#define KITERS (KDIM / BKB)  // 32

// SW128-style swizzle: XOR 16B-chunk index (bits[6:4]) with row%8 (bits[9:7])
#define SWZ(o) ((o) ^ (((o) >> 3) & 0x70))

// ---------------------------------------------------------------------------
// Device scratch (allocation-free)
// ---------------------------------------------------------------------------
__device__ __align__(1024) unsigned char g_x8[(size_t)MDIM * KDIM]; // 64 MB fp8 x [M,K]
__device__ __align__(1024) unsigned char g_w8[(size_t)NDIM * KDIM]; // 16 MB fp8 w^T [N,K]
__device__ unsigned int g_amax_bits[2];
__device__ float g_scales[3]; // xs, ws, (1/xs)*(1/ws)

// ---------------------------------------------------------------------------
// PTX helpers (family-portable: cp.async, ldmatrix, mma.sync)
// ---------------------------------------------------------------------------
__device__ __forceinline__ uint32_t smem_u32(const void* p) {
    uint32_t a;
    asm("{ .reg .u64 t; cvta.to.shared.u64 t, %1; cvt.u32.u64 %0, t; }" : "=r"(a) : "l"(p));
    return a;
}

#define CP_ASYNC16(dst, gsrc) \
    asm volatile("cp.async.cg.shared.global [%0], [%1], 16;" :: "r"(dst), "l"(gsrc) : "memory")
#define CP_COMMIT() asm volatile("cp.async.commit_group;" ::: "memory")
#define CP_WAIT(n)  asm volatile("cp.async.wait_group %0;" :: "n"(n) : "memory")

#define LDSM_X4(r0, r1, r2, r3, addr) \
    asm volatile("ldmatrix.sync.aligned.m8n8.x4.shared.b16 {%0,%1,%2,%3}, [%4];" \
        : "=r"(r0), "=r"(r1), "=r"(r2), "=r"(r3) : "r"(addr))

// fp8 e4m3 MMA, K=32, fp32 accumulate (PTX ISA: sm_89+, family-portable)
#define MMA16832(c, a, b) \
    asm volatile("mma.sync.aligned.m16n8k32.row.col.f32.e4m3.e4m3.f32 " \
        "{%0,%1,%2,%3}, {%4,%5,%6,%7}, {%8,%9}, {%0,%1,%2,%3};" \
        : "+f"((c)[0]), "+f"((c)[1]), "+f"((c)[2]), "+f"((c)[3]) \
        : "r"((a)[0]), "r"((a)[1]), "r"((a)[2]), "r"((a)[3]), "r"((b)[0]), "r"((b)[1]))

// ---------------------------------------------------------------------------
// Phase 1: amax reductions + scales
// ---------------------------------------------------------------------------
__global__ void reset_kernel() {
    g_amax_bits[0] = 0u;
    g_amax_bits[1] = 0u;
}

__global__ void amax_kernel(const float* __restrict__ p, long long n4, int slot) {
    float m = 0.0f;
    const float4* v = (const float4*)p;
    long long stride = (long long)gridDim.x * blockDim.x;
    for (long long i = (long long)blockIdx.x * blockDim.x + threadIdx.x; i < n4; i += stride) {
        float4 a = v[i];
        m = fmaxf(m, fmaxf(fmaxf(fabsf(a.x), fabsf(a.y)), fmaxf(fabsf(a.z), fabsf(a.w))));
    }
    #pragma unroll
    for (int o = 16; o; o >>= 1) m = fmaxf(m, __shfl_xor_sync(0xFFFFFFFFu, m, o));
    __shared__ float sm[32];
    if ((threadIdx.x & 31) == 0) sm[threadIdx.x >> 5] = m;
    __syncthreads();
    if (threadIdx.x < 32) {
        m = (threadIdx.x < (blockDim.x >> 5)) ? sm[threadIdx.x] : 0.0f;
        #pragma unroll
        for (int o = 16; o; o >>= 1) m = fmaxf(m, __shfl_xor_sync(0xFFFFFFFFu, m, o));
        if (threadIdx.x == 0) atomicMax(&g_amax_bits[slot], __float_as_uint(m));
    }
}

__global__ void scale_kernel() {
    float ax = __uint_as_float(g_amax_bits[0]);
    float aw = __uint_as_float(g_amax_bits[1]);
    float xs = 448.0f / fmaxf(ax, 1e-12f);
    float ws = 448.0f / fmaxf(aw, 1e-12f);
    g_scales[0] = xs;
    g_scales[1] = ws;
    g_scales[2] = (1.0f / xs) * (1.0f / ws);
}

__device__ __forceinline__ unsigned char q8(float v, float s) {
    return (unsigned char)__nv_cvt_float_to_fp8(v * s, __NV_SATFINITE, __NV_E4M3);
}

// ---------------------------------------------------------------------------
// Phase 2: quantize x [M,K] fp32 -> g_x8 [M,K] e4m3 bytes
// ---------------------------------------------------------------------------
__global__ void quant_x_kernel(const float* __restrict__ x) {
    size_t i = ((size_t)blockIdx.x * blockDim.x + threadIdx.x) * 16;
    float s = g_scales[0];
    uint32_t o[4];
    #pragma unroll
    for (int j = 0; j < 4; ++j) {
        float4 v = *(const float4*)(x + i + j * 4);
        o[j] = (uint32_t)q8(v.x, s)
             | ((uint32_t)q8(v.y, s) << 8)
             | ((uint32_t)q8(v.z, s) << 16)
             | ((uint32_t)q8(v.w, s) << 24);
    }
    *(uint4*)(g_x8 + i) = make_uint4(o[0], o[1], o[2], o[3]);
}

// ---------------------------------------------------------------------------
// Phase 3: weight [K,N] fp32 -> g_w8 [N,K] e4m3 bytes (transpose + quantize)
// ---------------------------------------------------------------------------
__global__ void quant_w_kernel(const float* __restrict__ w) {
    __shared__ unsigned char s[128 * 129];
    int k0 = blockIdx.x * 128;
    int n0 = blockIdx.y * 128;
    float ws = g_scales[1];
    #pragma unroll 4
    for (int it = 0; it < 16; ++it) {
        int p = it * 1024 + threadIdx.x * 4;
        int kl = p >> 7, nl = p & 127;
        float4 v = *(const float4*)&w[(size_t)(k0 + kl) * NDIM + n0 + nl];
        s[kl * 129 + nl + 0] = q8(v.x, ws);
        s[kl * 129 + nl + 1] = q8(v.y, ws);
        s[kl * 129 + nl + 2] = q8(v.z, ws);
        s[kl * 129 + nl + 3] = q8(v.w, ws);
    }
    __syncthreads();
    #pragma unroll
    for (int it = 0; it < 4; ++it) {
        int t = it * 256 + threadIdx.x;
        int nl = t >> 3, kg = t & 7;
        uint32_t o[4];
        #pragma unroll
        for (int j = 0; j < 4; ++j) {
            int kb = kg * 16 + j * 4;
            o[j] = (uint32_t)s[(kb + 0) * 129 + nl]
                 | ((uint32_t)s[(kb + 1) * 129 + nl] << 8)
                 | ((uint32_t)s[(kb + 2) * 129 + nl] << 16)
                 | ((uint32_t)s[(kb + 3) * 129 + nl] << 24);
        }
        *(uint4*)(g_w8 + (size_t)(n0 + nl) * KDIM + k0 + kg * 16) = make_uint4(o[0], o[1], o[2], o[3]);
    }
}

// ---------------------------------------------------------------------------
// Phase 4: GEMM. A = g_x8 [M,K] row-major, B = g_w8 [N,K] (TN).
// CTA 128x256, 8 warps (2x4), warp tile 64x64, 4-stage pipeline.
// ---------------------------------------------------------------------------
#define A_STAGE_BYTES (BM * BKB)             // 16384
#define B_STAGE_BYTES (BN * BKB)             // 32768
#define SMEM_TOTAL (STAGES * (A_STAGE_BYTES + B_STAGE_BYTES))  // 196608

__global__ void __launch_bounds__(256, 1) gemm_kernel(float* __restrict__ out) {
    extern __shared__ char smem[];
    const uint32_t sb = smem_u32(smem);
    const int tid = threadIdx.x;
    const int lane = tid & 31;
    const int wid = tid >> 5;
    const int warp_m = wid & 1;   // 2 warps along M (64 rows)
    const int warp_n = wid >> 1;  // 4 warps along N (64 cols)
    const int m0 = blockIdx.y * BM;
    const int n0 = blockIdx.x * BN;

    const uint64_t Ag = __cvta_generic_to_global(g_x8 + (size_t)m0 * KDIM);
    const uint64_t Bg = __cvta_generic_to_global(g_w8 + (size_t)n0 * KDIM);

    // one stage: A 128 rows x 8 chunks (1024 cp) + B 256 rows x 8 chunks (2048 cp)
    auto load_stage = [&](int stage, int kblk) {
        uint32_t abase = sb + stage * A_STAGE_BYTES;
        uint32_t bbase = sb + STAGES * A_STAGE_BYTES + stage * B_STAGE_BYTES;
        uint64_t koff = (uint64_t)kblk * BKB;
        #pragma unroll
        for (int i = 0; i < 4; ++i) {
            int c = tid + i * 256;
            int row = c >> 3, col = c & 7;
            CP_ASYNC16(abase + SWZ(row * 128 + col * 16),
                       Ag + (uint64_t)row * KDIM + koff + col * 16);
        }
        #pragma unroll
        for (int i = 0; i < 8; ++i) {
            int c = tid + i * 256;
            int row = c >> 3, col = c & 7;
            CP_ASYNC16(bbase + SWZ(row * 128 + col * 16),
                       Bg + (uint64_t)row * KDIM + koff + col * 16);
        }
        CP_COMMIT();
    };

    load_stage(0, 0);
    load_stage(1, 1);
    load_stage(2, 2);

    float acc[4][8][4];
    #pragma unroll
    for (int mi = 0; mi < 4; ++mi)
        #pragma unroll
        for (int nj = 0; nj < 8; ++nj)
            #pragma unroll
            for (int r = 0; r < 4; ++r) acc[mi][nj][r] = 0.0f;

    // per-lane ldmatrix row/byte components
    const uint32_t a_row = warp_m * 64 + (lane & 15);
    const uint32_t a_kb  = (uint32_t)((lane >> 4) << 4);
    const uint32_t b_n   = warp_n * 64 + (lane & 7) + ((lane >> 4) << 3);
    const uint32_t b_kb  = (uint32_t)(((lane >> 3) & 1) << 4);

    #pragma unroll 1
    for (int it = 0; it < KITERS; ++it) {
        CP_WAIT(2);
        __syncthreads();
        if (it + 3 < KITERS) load_stage((it + 3) & 3, it + 3);

        uint32_t abase = sb + (it & 3) * A_STAGE_BYTES;
        uint32_t bbase = sb + STAGES * A_STAGE_BYTES + (it & 3) * B_STAGE_BYTES;

        #pragma unroll
        for (int ks = 0; ks < 4; ++ks) {
            uint32_t a[4][4], b[8][2];
            #pragma unroll
            for (int mi = 0; mi < 4; ++mi) {
                uint32_t off = (a_row + mi * 16) * 128 + ks * 32 + a_kb;
                LDSM_X4(a[mi][0], a[mi][1], a[mi][2], a[mi][3], abase + SWZ(off));
            }
            #pragma unroll
            for (int bh = 0; bh < 4; ++bh) {
                uint32_t off = (b_n + bh * 16) * 128 + ks * 32 + b_kb;
                LDSM_X4(b[2 * bh][0], b[2 * bh][1], b[2 * bh + 1][0], b[2 * bh + 1][1],
                        bbase + SWZ(off));
            }
            #pragma unroll
            for (int mi = 0; mi < 4; ++mi)
                #pragma unroll
                for (int nj = 0; nj < 8; ++nj)
                    MMA16832(acc[mi][nj], a[mi], b[nj]);
        }
    }

    // epilogue
    const float cs = g_scales[2];
    const int row_base = m0 + warp_m * 64 + (lane >> 2);
    const int col_base = n0 + warp_n * 64 + (lane & 3) * 2;
    #pragma unroll
    for (int mi = 0; mi < 4; ++mi) {
        #pragma unroll
        for (int nj = 0; nj < 8; ++nj) {
            int r = row_base + mi * 16;
            int c = col_base + nj * 8;
            float2 v0 = make_float2(acc[mi][nj][0] * cs, acc[mi][nj][1] * cs);
            float2 v1 = make_float2(acc[mi][nj][2] * cs, acc[mi][nj][3] * cs);
            *(float2*)(out + (size_t)r * NDIM + c) = v0;
            *(float2*)(out + (size_t)(r + 8) * NDIM + c) = v1;
        }
    }
}

// ---------------------------------------------------------------------------
// Launch
// ---------------------------------------------------------------------------
extern "C" void kernel_launch(void* const* d_in, const int* in_sizes, int n_in,
                              void* d_out, int out_size) {
    const float* x = (const float*)d_in[0];
    const float* w = (const float*)d_in[1];
    float* out = (float*)d_out;

    cudaFuncSetAttribute(gemm_kernel, cudaFuncAttributeMaxDynamicSharedMemorySize, SMEM_TOTAL);

    reset_kernel<<<1, 1>>>();
    amax_kernel<<<2048, 256>>>(x, (long long)MDIM * KDIM / 4, 0);
    amax_kernel<<<512, 256>>>(w, (long long)KDIM * NDIM / 4, 1);
    scale_kernel<<<1, 1>>>();
    quant_x_kernel<<<(int)(((size_t)MDIM * KDIM / 16) / 256), 256>>>(x);
    quant_w_kernel<<<dim3(KDIM / 128, NDIM / 128), 256>>>(w);
    gemm_kernel<<<dim3(NDIM / BN, MDIM / BM), 256, SMEM_TOTAL>>>(out);
}

// round 5
// speedup vs baseline: 1.2437x; 1.2296x over previous
#include <cuda_runtime.h>
#include <cuda_fp16.h>
#include <cuda_fp8.h>
#include <cstdint>

// ---------------------------------------------------------------------------
// out[M,N] = (fp8(x*xs) @ fp8(w^T*ws)^T) * (1/xs)*(1/ws), fp32 out
// M=16384, N=4096, K=4096
// R5: fp16-storage path (e4m3 values exact in fp16), m16n8k16 HMMA,
// CTA 128x128 / warp 64x32, 3-stage cp.async pipeline, 2 CTAs/SM.
// Exactly 4 kernel launches so ncu (-s 5, 2 harness launches) captures GEMM.
// ---------------------------------------------------------------------------
#define MDIM 16384
#define NDIM 4096
#define KDIM 4096

#define BM 128
#define BN 128
#define BK 64                // fp16 elements per stage row (128 bytes)
#define STAGES 3
#define KITERS (KDIM / BK)   // 64

#define SWZ(o) ((o) ^ (((o) >> 3) & 0x70))

// ---------------------------------------------------------------------------
// Device scratch (allocation-free)
// ---------------------------------------------------------------------------
__device__ __align__(1024) __half g_xh[(size_t)MDIM * KDIM]; // 128 MB
__device__ __align__(1024) __half g_wh[(size_t)NDIM * KDIM]; // 32 MB
__device__ unsigned int g_amax_bits[2] = {0u, 0u};           // zeroed at load; scale_kernel re-zeros
__device__ float g_scales[3];                                // xs, ws, (1/xs)*(1/ws)

// ---------------------------------------------------------------------------
// PTX helpers
// ---------------------------------------------------------------------------
__device__ __forceinline__ uint32_t smem_u32(const void* p) {
    uint32_t a;
    asm("{ .reg .u64 t; cvta.to.shared.u64 t, %1; cvt.u32.u64 %0, t; }" : "=r"(a) : "l"(p));
    return a;
}

#define CP_ASYNC16(dst, gsrc) \
    asm volatile("cp.async.cg.shared.global [%0], [%1], 16;" :: "r"(dst), "l"(gsrc) : "memory")
#define CP_COMMIT() asm volatile("cp.async.commit_group;" ::: "memory")
#define CP_WAIT(n)  asm volatile("cp.async.wait_group %0;" :: "n"(n) : "memory")

#define LDSM_X4(r0, r1, r2, r3, addr) \
    asm volatile("ldmatrix.sync.aligned.m8n8.x4.shared.b16 {%0,%1,%2,%3}, [%4];" \
        : "=r"(r0), "=r"(r1), "=r"(r2), "=r"(r3) : "r"(addr))

#define MMA16816(c, a, b) \
    asm volatile("mma.sync.aligned.m16n8k16.row.col.f32.f16.f16.f32 " \
        "{%0,%1,%2,%3}, {%4,%5,%6,%7}, {%8,%9}, {%0,%1,%2,%3};" \
        : "+f"((c)[0]), "+f"((c)[1]), "+f"((c)[2]), "+f"((c)[3]) \
        : "r"((a)[0]), "r"((a)[1]), "r"((a)[2]), "r"((a)[3]), "r"((b)[0]), "r"((b)[1]))

// ---------------------------------------------------------------------------
// Launch 0: fused amax over x (blocks 0..2047) and w (blocks 2048..2559)
// ---------------------------------------------------------------------------
__global__ void amax_all_kernel(const float* __restrict__ x, const float* __restrict__ w) {
    int slot;
    const float4* v;
    long long n4, b0, nb;
    if (blockIdx.x < 2048) {
        slot = 0; v = (const float4*)x; n4 = (long long)MDIM * KDIM / 4; b0 = blockIdx.x; nb = 2048;
    } else {
        slot = 1; v = (const float4*)w; n4 = (long long)KDIM * NDIM / 4; b0 = blockIdx.x - 2048; nb = 512;
    }
    float m = 0.0f;
    long long stride = nb * blockDim.x;
    for (long long i = b0 * blockDim.x + threadIdx.x; i < n4; i += stride) {
        float4 a = v[i];
        m = fmaxf(m, fmaxf(fmaxf(fabsf(a.x), fabsf(a.y)), fmaxf(fabsf(a.z), fabsf(a.w))));
    }
    #pragma unroll
    for (int o = 16; o; o >>= 1) m = fmaxf(m, __shfl_xor_sync(0xFFFFFFFFu, m, o));
    __shared__ float sm[32];
    if ((threadIdx.x & 31) == 0) sm[threadIdx.x >> 5] = m;
    __syncthreads();
    if (threadIdx.x < 32) {
        m = (threadIdx.x < (blockDim.x >> 5)) ? sm[threadIdx.x] : 0.0f;
        #pragma unroll
        for (int o = 16; o; o >>= 1) m = fmaxf(m, __shfl_xor_sync(0xFFFFFFFFu, m, o));
        if (threadIdx.x == 0) atomicMax(&g_amax_bits[slot], __float_as_uint(m));
    }
}

// ---------------------------------------------------------------------------
// Launch 1: scales + reset amax accumulators for the next replay
// ---------------------------------------------------------------------------
__global__ void scale_kernel() {
    float ax = __uint_as_float(g_amax_bits[0]);
    float aw = __uint_as_float(g_amax_bits[1]);
    float xs = 448.0f / fmaxf(ax, 1e-12f);
    float ws = 448.0f / fmaxf(aw, 1e-12f);
    g_scales[0] = xs;
    g_scales[1] = ws;
    g_scales[2] = (1.0f / xs) * (1.0f / ws);
    g_amax_bits[0] = 0u;
    g_amax_bits[1] = 0u;
}

__device__ __forceinline__ unsigned short q8h(float v, float s) {
    __nv_fp8_storage_t r = __nv_cvt_float_to_fp8(v * s, __NV_SATFINITE, __NV_E4M3);
    __half_raw hr = __nv_cvt_fp8_to_halfraw(r, __NV_E4M3);
    return hr.x;
}

// ---------------------------------------------------------------------------
// Launch 2: fused quantize. Blocks [0, 32768): x elementwise (8 elems/thread).
// Blocks [32768, 32768+1024): w 128x128 transpose tiles.
// ---------------------------------------------------------------------------
__global__ void quant_all_kernel(const float* __restrict__ x, const float* __restrict__ w) {
    if (blockIdx.x < 32768) {
        size_t i = ((size_t)blockIdx.x * blockDim.x + threadIdx.x) * 8;
        float s = g_scales[0];
        float4 v0 = *(const float4*)(x + i);
        float4 v1 = *(const float4*)(x + i + 4);
        uint4 packed;
        packed.x = (uint32_t)q8h(v0.x, s) | ((uint32_t)q8h(v0.y, s) << 16);
        packed.y = (uint32_t)q8h(v0.z, s) | ((uint32_t)q8h(v0.w, s) << 16);
        packed.z = (uint32_t)q8h(v1.x, s) | ((uint32_t)q8h(v1.y, s) << 16);
        packed.w = (uint32_t)q8h(v1.z, s) | ((uint32_t)q8h(v1.w, s) << 16);
        *(uint4*)(g_xh + i) = packed;
    } else {
        __shared__ unsigned short sbuf[128 * 129];
        int t = blockIdx.x - 32768;
        int k0 = (t & 31) * 128;
        int n0 = (t >> 5) * 128;
        float ws = g_scales[1];
        #pragma unroll 4
        for (int it = 0; it < 16; ++it) {
            int p = it * 1024 + threadIdx.x * 4;
            int kl = p >> 7, nl = p & 127;
            float4 v = *(const float4*)&w[(size_t)(k0 + kl) * NDIM + n0 + nl];
            sbuf[kl * 129 + nl + 0] = q8h(v.x, ws);
            sbuf[kl * 129 + nl + 1] = q8h(v.y, ws);
            sbuf[kl * 129 + nl + 2] = q8h(v.z, ws);
            sbuf[kl * 129 + nl + 3] = q8h(v.w, ws);
        }
        __syncthreads();
        #pragma unroll 2
        for (int it = 0; it < 8; ++it) {
            int tt = it * 256 + threadIdx.x;
            int nl = tt >> 4, kg = tt & 15;
            unsigned short h[8];
            #pragma unroll
            for (int i = 0; i < 8; ++i) h[i] = sbuf[(kg * 8 + i) * 129 + nl];
            uint4 packed;
            packed.x = (uint32_t)h[0] | ((uint32_t)h[1] << 16);
            packed.y = (uint32_t)h[2] | ((uint32_t)h[3] << 16);
            packed.z = (uint32_t)h[4] | ((uint32_t)h[5] << 16);
            packed.w = (uint32_t)h[6] | ((uint32_t)h[7] << 16);
            *(uint4*)(g_wh + (size_t)(n0 + nl) * KDIM + k0 + kg * 8) = packed;
        }
    }
}

// ---------------------------------------------------------------------------
// Launch 3: GEMM. A = g_xh [M,K], B = g_wh [N,K] (TN).
// CTA 128x128, 3-stage pipeline, 8 warps of 64x32, 2 CTAs/SM.
// ---------------------------------------------------------------------------
#define A_STAGE_BYTES (BM * BK * 2)          // 16384
#define B_STAGE_BYTES (BN * BK * 2)          // 16384
#define SMEM_TOTAL (STAGES * (A_STAGE_BYTES + B_STAGE_BYTES))  // 98304

__global__ void __launch_bounds__(256, 2) gemm_kernel(float* __restrict__ out) {
    extern __shared__ char smem[];
    const uint32_t sb = smem_u32(smem);
    const int tid = threadIdx.x;
    const int lane = tid & 31;
    const int wid = tid >> 5;
    const int warp_m = wid & 1;
    const int warp_n = wid >> 1;
    const int m0 = blockIdx.y * BM;
    const int n0 = blockIdx.x * BN;

    const uint64_t Ag = __cvta_generic_to_global(g_xh + (size_t)m0 * KDIM);
    const uint64_t Bg = __cvta_generic_to_global(g_wh + (size_t)n0 * KDIM);

    auto load_stage = [&](int stage, int kblk) {
        uint32_t abase = sb + stage * A_STAGE_BYTES;
        uint32_t bbase = sb + STAGES * A_STAGE_BYTES + stage * B_STAGE_BYTES;
        uint64_t koff = (uint64_t)kblk * (BK * 2);
        #pragma unroll
        for (int i = 0; i < 4; ++i) {
            int c = tid + i * 256;
            int row = c >> 3, col = c & 7;
            CP_ASYNC16(abase + SWZ(row * 128 + col * 16),
                       Ag + (uint64_t)row * (KDIM * 2) + koff + col * 16);
        }
        #pragma unroll
        for (int i = 0; i < 4; ++i) {
            int c = tid + i * 256;
            int row = c >> 3, col = c & 7;
            CP_ASYNC16(bbase + SWZ(row * 128 + col * 16),
                       Bg + (uint64_t)row * (KDIM * 2) + koff + col * 16);
        }
        CP_COMMIT();
    };

    load_stage(0, 0);
    load_stage(1, 1);

    float acc[4][4][4];
    #pragma unroll
    for (int mi = 0; mi < 4; ++mi)
        #pragma unroll
        for (int nj = 0; nj < 4; ++nj)
            #pragma unroll
            for (int r = 0; r < 4; ++r) acc[mi][nj][r] = 0.0f;

    const uint32_t a_row = warp_m * 64 + (lane & 15);
    const uint32_t a_kb  = (uint32_t)((lane >> 4) << 4);
    const uint32_t b_n   = warp_n * 32 + (lane & 7) + ((lane >> 4) << 3);
    const uint32_t b_kb  = (uint32_t)(((lane >> 3) & 1) << 4);

    int stage = 0;
    #pragma unroll 1
    for (int it = 0; it < KITERS; ++it) {
        CP_WAIT(1);
        __syncthreads();
        if (it + 2 < KITERS) {
            int ps = stage + 2;
            if (ps >= STAGES) ps -= STAGES;
            load_stage(ps, it + 2);
        }

        uint32_t abase = sb + stage * A_STAGE_BYTES;
        uint32_t bbase = sb + STAGES * A_STAGE_BYTES + stage * B_STAGE_BYTES;

        #pragma unroll
        for (int ks = 0; ks < 4; ++ks) {
            uint32_t a[4][4], b[4][2];
            #pragma unroll
            for (int mi = 0; mi < 4; ++mi) {
                uint32_t off = (a_row + mi * 16) * 128 + ks * 32 + a_kb;
                LDSM_X4(a[mi][0], a[mi][1], a[mi][2], a[mi][3], abase + SWZ(off));
            }
            #pragma unroll
            for (int bh = 0; bh < 2; ++bh) {
                uint32_t off = (b_n + bh * 16) * 128 + ks * 32 + b_kb;
                LDSM_X4(b[2 * bh][0], b[2 * bh][1], b[2 * bh + 1][0], b[2 * bh + 1][1],
                        bbase + SWZ(off));
            }
            #pragma unroll
            for (int mi = 0; mi < 4; ++mi)
                #pragma unroll
                for (int nj = 0; nj < 4; ++nj)
                    MMA16816(acc[mi][nj], a[mi], b[nj]);
        }
        if (++stage == STAGES) stage = 0;
    }

    const float cs = g_scales[2];
    const int row_base = m0 + warp_m * 64 + (lane >> 2);
    const int col_base = n0 + warp_n * 32 + (lane & 3) * 2;
    #pragma unroll
    for (int mi = 0; mi < 4; ++mi) {
        #pragma unroll
        for (int nj = 0; nj < 4; ++nj) {
            int r = row_base + mi * 16;
            int c = col_base + nj * 8;
            float2 v0 = make_float2(acc[mi][nj][0] * cs, acc[mi][nj][1] * cs);
            float2 v1 = make_float2(acc[mi][nj][2] * cs, acc[mi][nj][3] * cs);
            *(float2*)(out + (size_t)r * NDIM + c) = v0;
            *(float2*)(out + (size_t)(r + 8) * NDIM + c) = v1;
        }
    }
}

// ---------------------------------------------------------------------------
// Launch: exactly 4 kernels (ncu -s 5 + 2 harness launches => captures GEMM)
// ---------------------------------------------------------------------------
extern "C" void kernel_launch(void* const* d_in, const int* in_sizes, int n_in,
                              void* d_out, int out_size) {
    const float* x = (const float*)d_in[0];
    const float* w = (const float*)d_in[1];
    float* out = (float*)d_out;

    cudaFuncSetAttribute(gemm_kernel, cudaFuncAttributeMaxDynamicSharedMemorySize, SMEM_TOTAL);

    amax_all_kernel<<<2560, 256>>>(x, w);
    scale_kernel<<<1, 1>>>();
    quant_all_kernel<<<32768 + 1024, 256>>>(x, w);
    gemm_kernel<<<dim3(NDIM / BN, MDIM / BM), 256, SMEM_TOTAL>>>(out);
}